// round 12
// baseline (speedup 1.0000x reference)
#include <cuda_runtime.h>
#include <cstdint>

#define BB 8
#define NN 256
#define HH 128
#define EPSF 1e-20f

#define GRIDSZ 512
#define TPB    256

// Scratch (allocation-free rule: __device__ globals)
__device__ float g_Ux[BB * NN * HH];
__device__ float g_Vx[BB * NN * HH];
__device__ unsigned int g_bar;   // monotonic across graph replays

__device__ __forceinline__ float dot4(float4 a, float4 b, float c) {
    return fmaf(a.x, b.x, fmaf(a.y, b.y, fmaf(a.z, b.z, fmaf(a.w, b.w, c))));
}

// ---------------------------------------------------------------------------
// FUSED v3: R10-proven linear (coalesced smem staging, ~40 regs) + proven
// monotonic grid barrier + byte-identical R11 edge loop (47.9us @ 72% DRAM).
// grid 512, launch_bounds(256,4): reg budget 64 == what R11 edge compiled to;
// capacity 592 >= 512 -> all resident, barrier deadlock-free.
// Eliminates the ~10us two-kernel gap (R7 evidence: fused total == kernel).
// Smem: linear (ws 16.9K + xs 16K) and edge (msk 1K + sh 32K) alias one pool.
// ---------------------------------------------------------------------------
__global__ __launch_bounds__(TPB, 4) void fused_kernel(
    const float* __restrict__ x, const float* __restrict__ eg,
    const float* __restrict__ mask,
    const float* __restrict__ Uw, const float* __restrict__ Ub,
    const float* __restrict__ Vw, const float* __restrict__ Vb,
    float* __restrict__ out)
{
    __shared__ __align__(16) char pool[33 * 1024 + 256];
    const int t = threadIdx.x;

    // ---------------- Phase 1: linear (all 512 blocks, 1 unit each) --------
    {
        float*  ws = reinterpret_cast<float*>(pool);                    // 32*132 floats
        float4* xs = reinterpret_cast<float4*>(pool + 32 * 132 * 4);    // 32*32 float4

        const int bx = blockIdx.x;
        const int r0 = (bx & 63) * 32;          // row tile 0..63
        const int yy = bx >> 6;                 // 0..7
        const bool isU = (yy < 4);
        const int o0 = (yy & 3) * 32;

        const float4* Wg = reinterpret_cast<const float4*>(isU ? Uw : Vw) + (size_t)o0 * 32;
        const float4* Xg = reinterpret_cast<const float4*>(x) + (size_t)r0 * 32;

#pragma unroll
        for (int i = t; i < 1024; i += 256) {
            const int row = i >> 5, c = i & 31;
            reinterpret_cast<float4*>(ws + row * 132)[c] = Wg[i];
            xs[i] = Xg[i];
        }
        __syncthreads();

        const int o_l = t & 31;
        const int wr  = t >> 5;
        const float4* wrow = reinterpret_cast<const float4*>(ws + o_l * 132);
        const float4* xrow = xs + (wr * 4) * 32;

        float a0 = 0.f, a1 = 0.f, a2 = 0.f, a3 = 0.f;
#pragma unroll 8
        for (int k4 = 0; k4 < 32; k4++) {
            const float4 w = wrow[k4];          // conflict-free LDS.128
            a0 = dot4(xrow[k4],      w, a0);
            a1 = dot4(xrow[32 + k4], w, a1);
            a2 = dot4(xrow[64 + k4], w, a2);
            a3 = dot4(xrow[96 + k4], w, a3);
        }

        const int o = o0 + o_l;
        const float bias = isU ? Ub[o] : Vb[o];
        float* dst = isU ? g_Ux : g_Vx;
        const int r = r0 + wr * 4;
        dst[(size_t)(r + 0) * HH + o] = mask[r + 0] * (a0 + bias);
        dst[(size_t)(r + 1) * HH + o] = mask[r + 1] * (a1 + bias);
        dst[(size_t)(r + 2) * HH + o] = mask[r + 2] * (a2 + bias);
        dst[(size_t)(r + 3) * HH + o] = mask[r + 3] * (a3 + bias);
    }

    // ---------------- Grid-wide barrier (monotonic, replay-safe) ----------
    __syncthreads();
    if (t == 0) {
        __threadfence();
        const unsigned int ticket = atomicAdd(&g_bar, 1u);
        const unsigned int target = ticket - (ticket % GRIDSZ) + GRIDSZ;
        for (;;) {
            unsigned int cur;
            asm volatile("ld.acquire.gpu.global.u32 %0, [%1];" : "=r"(cur) : "l"(&g_bar));
            if ((int)(cur - target) >= 0) break;
            __nanosleep(64);
        }
    }
    __syncthreads();

    // ---------------- Phase 2: edge (byte-identical R11 loop) -------------
    const int lane = t & 31;
    const int w    = t >> 5;            // 0..7 : j-chunk
    const int bi0  = blockIdx.x * 4;
    const int b    = bi0 >> 8;          // 4 | 256 -> same b for all 4 tiles

    float* msk = reinterpret_cast<float*>(pool);                         // NN floats
    float4 (*sh)[4][8][32] = reinterpret_cast<float4 (*)[4][8][32]>(pool + 1024);

    msk[t] = mask[b * NN + t];
    __syncthreads();

    const int j0 = w * 32;
    const float4* ep = reinterpret_cast<const float4*>(eg)
                       + ((size_t)bi0 * NN + j0) * 32 + lane;
    const float4* vp = reinterpret_cast<const float4*>(g_Vx)
                       + ((size_t)b * NN + j0) * 32 + lane;
    const float* mp = &msk[j0];

    float4 s00 = {0,0,0,0}, s01 = {0,0,0,0}, s02 = {0,0,0,0}, s03 = {0,0,0,0};
    float4 s10 = {0,0,0,0}, s11 = {0,0,0,0}, s12 = {0,0,0,0}, s13 = {0,0,0,0};

    const size_t TS = (size_t)NN * 32;  // tile stride in float4

#pragma unroll 2
    for (int jj = 0; jj < 32; jj++) {
        const float4 e0 = __ldcs(ep);
        const float4 e1 = __ldcs(ep + TS);
        const float4 e2 = __ldcs(ep + 2 * TS);
        const float4 e3 = __ldcs(ep + 3 * TS);
        ep += 32;
        const float4 v = __ldg(vp); vp += 32;
        const float mj = mp[jj];
        float4 vm;
        vm.x = mj * v.x; vm.y = mj * v.y; vm.z = mj * v.z; vm.w = mj * v.w;

        s00.x = fmaf(e0.x, mj, s00.x); s10.x = fmaf(e0.x, vm.x, s10.x);
        s00.y = fmaf(e0.y, mj, s00.y); s10.y = fmaf(e0.y, vm.y, s10.y);
        s00.z = fmaf(e0.z, mj, s00.z); s10.z = fmaf(e0.z, vm.z, s10.z);
        s00.w = fmaf(e0.w, mj, s00.w); s10.w = fmaf(e0.w, vm.w, s10.w);

        s01.x = fmaf(e1.x, mj, s01.x); s11.x = fmaf(e1.x, vm.x, s11.x);
        s01.y = fmaf(e1.y, mj, s01.y); s11.y = fmaf(e1.y, vm.y, s11.y);
        s01.z = fmaf(e1.z, mj, s01.z); s11.z = fmaf(e1.z, vm.z, s11.z);
        s01.w = fmaf(e1.w, mj, s01.w); s11.w = fmaf(e1.w, vm.w, s11.w);

        s02.x = fmaf(e2.x, mj, s02.x); s12.x = fmaf(e2.x, vm.x, s12.x);
        s02.y = fmaf(e2.y, mj, s02.y); s12.y = fmaf(e2.y, vm.y, s12.y);
        s02.z = fmaf(e2.z, mj, s02.z); s12.z = fmaf(e2.z, vm.z, s12.z);
        s02.w = fmaf(e2.w, mj, s02.w); s12.w = fmaf(e2.w, vm.w, s12.w);

        s03.x = fmaf(e3.x, mj, s03.x); s13.x = fmaf(e3.x, vm.x, s13.x);
        s03.y = fmaf(e3.y, mj, s03.y); s13.y = fmaf(e3.y, vm.y, s13.y);
        s03.z = fmaf(e3.z, mj, s03.z); s13.z = fmaf(e3.z, vm.z, s13.z);
        s03.w = fmaf(e3.w, mj, s03.w); s13.w = fmaf(e3.w, vm.w, s13.w);
    }

    __syncthreads();   // ensure msk reads done before pool reuse by sh
    (*sh)[0][w][lane] = s00;
    (*sh)[1][w][lane] = s01;
    (*sh)[2][w][lane] = s02;
    (*sh)[3][w][lane] = s03;
    __syncthreads();

    // fold gate-sums into tile-major, then reuse for value-sums
    float4 a0, a1;
    if (t < 128) {
        const int tile = t >> 5, l = t & 31;
        a0 = (*sh)[tile][0][l];
#pragma unroll
        for (int k = 1; k < 8; k++) {
            const float4 c = (*sh)[tile][k][l];
            a0.x += c.x; a0.y += c.y; a0.z += c.z; a0.w += c.w;
        }
    }
    __syncthreads();
    (*sh)[0][w][lane] = s10;
    (*sh)[1][w][lane] = s11;
    (*sh)[2][w][lane] = s12;
    (*sh)[3][w][lane] = s13;
    __syncthreads();

    if (t < 128) {
        const int tile = t >> 5, l = t & 31;
        a1 = (*sh)[tile][0][l];
#pragma unroll
        for (int k = 1; k < 8; k++) {
            const float4 c = (*sh)[tile][k][l];
            a1.x += c.x; a1.y += c.y; a1.z += c.z; a1.w += c.w;
        }
        const int bi = bi0 + tile;
        const float mi = mask[b * NN + (bi & 255)];
        const float4 ux = reinterpret_cast<const float4*>(g_Ux)[(size_t)bi * 32 + l];
        float4 o;
        o.x = ux.x + (mi * a1.x) / (EPSF + mi * a0.x);
        o.y = ux.y + (mi * a1.y) / (EPSF + mi * a0.y);
        o.z = ux.z + (mi * a1.z) / (EPSF + mi * a0.z);
        o.w = ux.w + (mi * a1.w) / (EPSF + mi * a0.w);
        reinterpret_cast<float4*>(out)[(size_t)bi * 32 + l] = o;
    }
}

extern "C" void kernel_launch(void* const* d_in, const int* in_sizes, int n_in,
                              void* d_out, int out_size)
{
    const float* x   = (const float*)d_in[0];
    const float* eg  = (const float*)d_in[1];
    const float* msk = (const float*)d_in[2];
    const float* Uw  = (const float*)d_in[3];
    const float* Ub  = (const float*)d_in[4];
    const float* Vw  = (const float*)d_in[5];
    const float* Vb  = (const float*)d_in[6];
    float* out = (float*)d_out;

    fused_kernel<<<GRIDSZ, TPB>>>(x, eg, msk, Uw, Ub, Vw, Vb, out);
}

// round 14
// speedup vs baseline: 1.0393x; 1.0393x over previous
#include <cuda_runtime.h>
#include <cstdint>

#define BB 8
#define NN 256
#define HH 128
#define EPSF 1e-20f

// Scratch (allocation-free rule: __device__ globals; zero-init at load)
__device__ float g_Ux[BB * NN * HH];
__device__ float g_Vx[BB * NN * HH];
__device__ float4 g_p0[512][2][4][32];   // gate partial  [group][half][tile][lane]
__device__ float4 g_p1[512][2][4][32];   // value partial
__device__ unsigned int g_cnt[512];      // monotonic group tickets (2/replay)

__device__ __forceinline__ float dot4(float4 a, float4 b, float c) {
    return fmaf(a.x, b.x, fmaf(a.y, b.y, fmaf(a.z, b.z, fmaf(a.w, b.w, c))));
}

// ---------------------------------------------------------------------------
// Kernel 1: R10-proven coalesced smem-staged linear (unchanged, ~5us,
// smem-crossbar-bound -- not worth touching).
// ---------------------------------------------------------------------------
__global__ __launch_bounds__(256) void linear_kernel(
    const float* __restrict__ x, const float* __restrict__ mask,
    const float* __restrict__ Uw, const float* __restrict__ Ub,
    const float* __restrict__ Vw, const float* __restrict__ Vb)
{
    __shared__ float  ws[32 * 132];
    __shared__ float4 xs[32 * 32];

    const int t  = threadIdx.x;
    const int r0 = blockIdx.x * 32;
    const bool isU = (blockIdx.y < 4);
    const int o0 = (blockIdx.y & 3) * 32;

    const float4* Wg = reinterpret_cast<const float4*>(isU ? Uw : Vw) + (size_t)o0 * 32;
    const float4* Xg = reinterpret_cast<const float4*>(x) + (size_t)r0 * 32;

#pragma unroll
    for (int i = t; i < 1024; i += 256) {
        const int row = i >> 5, c = i & 31;
        reinterpret_cast<float4*>(ws + row * 132)[c] = Wg[i];
        xs[i] = Xg[i];
    }
    __syncthreads();

    const int o_l = t & 31;
    const int wr  = t >> 5;
    const float4* wrow = reinterpret_cast<const float4*>(ws + o_l * 132);
    const float4* xrow = xs + (wr * 4) * 32;

    float a0 = 0.f, a1 = 0.f, a2 = 0.f, a3 = 0.f;
#pragma unroll 8
    for (int k4 = 0; k4 < 32; k4++) {
        const float4 w = wrow[k4];
        a0 = dot4(xrow[k4],      w, a0);
        a1 = dot4(xrow[32 + k4], w, a1);
        a2 = dot4(xrow[64 + k4], w, a2);
        a3 = dot4(xrow[96 + k4], w, a3);
    }

    const int o = o0 + o_l;
    const float bias = isU ? Ub[o] : Vb[o];
    float* dst = isU ? g_Ux : g_Vx;
    const int r = r0 + wr * 4;
    dst[(size_t)(r + 0) * HH + o] = mask[r + 0] * (a0 + bias);
    dst[(size_t)(r + 1) * HH + o] = mask[r + 1] * (a1 + bias);
    dst[(size_t)(r + 2) * HH + o] = mask[r + 2] * (a2 + bias);
    dst[(size_t)(r + 3) * HH + o] = mask[r + 3] * (a3 + bias);
}

// ---------------------------------------------------------------------------
// Kernel 2 (j-half + last-block finish): grid 1024. Block = (group g of 4
// tiles, half h of j-range). Half-duration blocks -> 1024/148 = 6.92
// slots/SM, imbalance ~1% (R11's 512 blocks: 4-vs-3 per SM = 16% tax,
// measured balance 0.865). v-reuse x4 kept. Partials -> global scratch;
// per-group monotonic ticket; second arrival combines (ldcg) + epilogue.
// ---------------------------------------------------------------------------
__global__ __launch_bounds__(256, 4) void edge_kernel(
    const float* __restrict__ eg, const float* __restrict__ mask,
    float* __restrict__ out)
{
    const int t    = threadIdx.x;
    const int lane = t & 31;
    const int w    = t >> 5;            // 0..7 : j-subchunk
    const int bx   = blockIdx.x;
    const int g    = bx >> 1;           // group 0..511
    const int h    = bx & 1;            // j-half
    const int bi0  = g * 4;
    const int b    = bi0 >> 8;

    __shared__ float  msk[NN];
    __shared__ float4 sh[2][4][8][32];  // 32KB
    __shared__ unsigned int am_second;

    msk[t] = mask[b * NN + t];
    __syncthreads();

    const int j0 = h * 128 + w * 16;
    const float4* ep = reinterpret_cast<const float4*>(eg)
                       + ((size_t)bi0 * NN + j0) * 32 + lane;
    const float4* vp = reinterpret_cast<const float4*>(g_Vx)
                       + ((size_t)b * NN + j0) * 32 + lane;
    const float* mp = &msk[j0];

    float4 s00 = {0,0,0,0}, s01 = {0,0,0,0}, s02 = {0,0,0,0}, s03 = {0,0,0,0};
    float4 s10 = {0,0,0,0}, s11 = {0,0,0,0}, s12 = {0,0,0,0}, s13 = {0,0,0,0};

    const size_t TS = (size_t)NN * 32;  // tile stride in float4

#pragma unroll 2
    for (int jj = 0; jj < 16; jj++) {
        const float4 e0 = __ldcs(ep);
        const float4 e1 = __ldcs(ep + TS);
        const float4 e2 = __ldcs(ep + 2 * TS);
        const float4 e3 = __ldcs(ep + 3 * TS);
        ep += 32;
        const float4 v = __ldg(vp); vp += 32;
        const float mj = mp[jj];
        float4 vm;
        vm.x = mj * v.x; vm.y = mj * v.y; vm.z = mj * v.z; vm.w = mj * v.w;

        s00.x = fmaf(e0.x, mj, s00.x); s10.x = fmaf(e0.x, vm.x, s10.x);
        s00.y = fmaf(e0.y, mj, s00.y); s10.y = fmaf(e0.y, vm.y, s10.y);
        s00.z = fmaf(e0.z, mj, s00.z); s10.z = fmaf(e0.z, vm.z, s10.z);
        s00.w = fmaf(e0.w, mj, s00.w); s10.w = fmaf(e0.w, vm.w, s10.w);

        s01.x = fmaf(e1.x, mj, s01.x); s11.x = fmaf(e1.x, vm.x, s11.x);
        s01.y = fmaf(e1.y, mj, s01.y); s11.y = fmaf(e1.y, vm.y, s11.y);
        s01.z = fmaf(e1.z, mj, s01.z); s11.z = fmaf(e1.z, vm.z, s11.z);
        s01.w = fmaf(e1.w, mj, s01.w); s11.w = fmaf(e1.w, vm.w, s11.w);

        s02.x = fmaf(e2.x, mj, s02.x); s12.x = fmaf(e2.x, vm.x, s12.x);
        s02.y = fmaf(e2.y, mj, s02.y); s12.y = fmaf(e2.y, vm.y, s12.y);
        s02.z = fmaf(e2.z, mj, s02.z); s12.z = fmaf(e2.z, vm.z, s12.z);
        s02.w = fmaf(e2.w, mj, s02.w); s12.w = fmaf(e2.w, vm.w, s12.w);

        s03.x = fmaf(e3.x, mj, s03.x); s13.x = fmaf(e3.x, vm.x, s13.x);
        s03.y = fmaf(e3.y, mj, s03.y); s13.y = fmaf(e3.y, vm.y, s13.y);
        s03.z = fmaf(e3.z, mj, s03.z); s13.z = fmaf(e3.z, vm.z, s13.z);
        s03.w = fmaf(e3.w, mj, s03.w); s13.w = fmaf(e3.w, vm.w, s13.w);
    }

    sh[0][0][w][lane] = s00;  sh[1][0][w][lane] = s10;
    sh[0][1][w][lane] = s01;  sh[1][1][w][lane] = s11;
    sh[0][2][w][lane] = s02;  sh[1][2][w][lane] = s12;
    sh[0][3][w][lane] = s03;  sh[1][3][w][lane] = s13;
    __syncthreads();

    float4 a0, a1;
    if (t < 128) {
        const int tile = t >> 5, l = t & 31;
        a0 = sh[0][tile][0][l];
        a1 = sh[1][tile][0][l];
#pragma unroll
        for (int k = 1; k < 8; k++) {
            const float4 c0 = sh[0][tile][k][l];
            const float4 c1 = sh[1][tile][k][l];
            a0.x += c0.x; a0.y += c0.y; a0.z += c0.z; a0.w += c0.w;
            a1.x += c1.x; a1.y += c1.y; a1.z += c1.z; a1.w += c1.w;
        }
        // publish this half's partials
        g_p0[g][h][tile][l] = a0;
        g_p1[g][h][tile][l] = a1;
    }
    __threadfence();
    __syncthreads();

    if (t == 0) am_second = atomicAdd(&g_cnt[g], 1u) & 1u;
    __syncthreads();

    if (am_second && t < 128) {
        const int tile = t >> 5, l = t & 31;
        // other half's partials are L2-visible (producer: STG+fence+atomic)
        const float4 o0 = __ldcg(&g_p0[g][1 - h][tile][l]);
        const float4 o1 = __ldcg(&g_p1[g][1 - h][tile][l]);
        a0.x += o0.x; a0.y += o0.y; a0.z += o0.z; a0.w += o0.w;
        a1.x += o1.x; a1.y += o1.y; a1.z += o1.z; a1.w += o1.w;

        const int bi = bi0 + tile;
        const float mi = msk[bi & 255];
        const float4 ux = reinterpret_cast<const float4*>(g_Ux)[(size_t)bi * 32 + l];
        float4 o;
        o.x = ux.x + (mi * a1.x) / (EPSF + mi * a0.x);
        o.y = ux.y + (mi * a1.y) / (EPSF + mi * a0.y);
        o.z = ux.z + (mi * a1.z) / (EPSF + mi * a0.z);
        o.w = ux.w + (mi * a1.w) / (EPSF + mi * a0.w);
        reinterpret_cast<float4*>(out)[(size_t)bi * 32 + l] = o;
    }
}

extern "C" void kernel_launch(void* const* d_in, const int* in_sizes, int n_in,
                              void* d_out, int out_size)
{
    const float* x   = (const float*)d_in[0];
    const float* eg  = (const float*)d_in[1];
    const float* msk = (const float*)d_in[2];
    const float* Uw  = (const float*)d_in[3];
    const float* Ub  = (const float*)d_in[4];
    const float* Vw  = (const float*)d_in[5];
    const float* Vb  = (const float*)d_in[6];
    float* out = (float*)d_out;

    dim3 lgrid(64, 8);
    linear_kernel<<<lgrid, 256>>>(x, msk, Uw, Ub, Vw, Vb);
    edge_kernel<<<1024, 256>>>(eg, msk, out);
}